// round 5
// baseline (speedup 1.0000x reference)
#include <cuda_runtime.h>
#include <cuda_bf16.h>

#define WIDTH 4096
#define HALFW 2048
#define DEPTH 32
#define BATCH 16384

// Per-stage (cos, sin) tables, built by prologue kernel. 512 KB __device__ global.
__device__ float2 g_tab[DEPTH][HALFW];

__global__ void ob_tables(const float* __restrict__ P) {
    int idx = blockIdx.x * blockDim.x + threadIdx.x;
    if (idx >= DEPTH * HALFW) return;
    int s = idx >> 11, k = idx & 2047;
    float th = P[k * DEPTH + s];            // params is (HALF, DEPTH) row-major
    g_tab[s][k] = make_float2(cosf(th), sinf(th));
}

__device__ __forceinline__ int rotl12(int v, int sm) {
    return ((v << sm) | (v >> (12 - sm))) & 0xFFF;
}

// Fixed layout: b_s[j] = z_s[rotl_{4+s}(j)].
// Stage s: pair rotation on bit d=(7-s) mod 12, angle index rotl_{(s+4)%12}(j) & 0x7FF,
// sign from bit d of j. Input: b_0[j] = X[rotl4(j)]. Output: out[j] = b_32[j] (identity).
__global__ __launch_bounds__(256, 2)
void ob_main(const float* __restrict__ X, float* __restrict__ O) {
    __shared__ float2 stab[HALFW];     // 16 KB: current stage's (cos,sin) table
    __shared__ float2 ex[2][1024];     // 16 KB: cross-warp exchange buffer

    const int tid  = threadIdx.x;
    const int rp   = tid >> 7;         // row-pair within CTA (0/1)
    const int t    = tid & 127;        // thread within row group
    const int lane = t & 31;           // j bits 0..4
    const int w    = t >> 5;           // j bits 10..11
    const long r0base = (long)blockIdx.x * 4 + rp * 2;

    float2 x[32];                      // .x = row r0base, .y = row r0base+1; reg idx = j bits 5..9

    // ---- input: b_0[j] = X[row][rotl4(j)] ----
    // rotl4(j) = (lane<<4) | ((r&7)<<9) | (r>>3) | (w<<2); the 4 consecutive floats
    // at (r>>3)=0..3 are registers m, m+8, m+16, m+24 -> one float4 each.
    {
        const float4* s0 = (const float4*)(X + r0base * WIDTH);
        const float4* s1 = (const float4*)(X + (r0base + 1) * WIDTH);
        #pragma unroll
        for (int m = 0; m < 8; ++m) {
            int i4 = (lane << 2) | (m << 7) | w;
            float4 v0 = s0[i4];
            float4 v1 = s1[i4];
            x[m].x = v0.x; x[m + 8].x = v0.y; x[m + 16].x = v0.z; x[m + 24].x = v0.w;
            x[m].y = v1.x; x[m + 8].y = v1.y; x[m + 16].y = v1.z; x[m + 24].y = v1.w;
        }
    }

    // ---- 32 stages ----
    #pragma unroll 1
    for (int s = 0; s < DEPTH; ++s) {
        __syncthreads();   // previous stage done reading stab
        {
            const float4* gsrc = (const float4*)&g_tab[s][0];
            float4* sdst = (float4*)&stab[0];
            #pragma unroll
            for (int c = 0; c < 4; ++c) sdst[c * 256 + tid] = gsrc[c * 256 + tid];
        }
        __syncthreads();

        const int sm = (s + 4) % 12;
        int d = (7 - s) % 12; if (d < 0) d += 12;
        const int ktw = rotl12((w << 10) | lane, sm);

        if (d >= 5 && d <= 9) {
            // register stage: partner differs in bit (d-5) of r
            const int rb = 1 << (d - 5);
            #pragma unroll
            for (int r0 = 0; r0 < 32; ++r0) {
                if (r0 & rb) continue;
                const int r1 = r0 | rb;
                int k = (ktw | rotl12(r0 << 5, sm)) & 0x7FF;
                float2 cs = stab[k];
                float2 a = x[r0], b = x[r1];
                x[r0].x = fmaf(cs.x, a.x,  cs.y * b.x);
                x[r0].y = fmaf(cs.x, a.y,  cs.y * b.y);
                x[r1].x = fmaf(cs.x, b.x, -cs.y * a.x);
                x[r1].y = fmaf(cs.x, b.y, -cs.y * a.y);
            }
        } else if (d <= 4) {
            // lane stage: partner lane ^ (1<<d)
            const int pb = 1 << d;
            const float sgn = (lane & pb) ? -1.f : 1.f;
            #pragma unroll
            for (int r = 0; r < 32; ++r) {
                int k = (ktw | rotl12(r << 5, sm)) & 0x7FF;
                float2 cs = stab[k];
                float px = __shfl_xor_sync(0xffffffffu, x[r].x, pb);
                float py = __shfl_xor_sync(0xffffffffu, x[r].y, pb);
                x[r].x = fmaf(cs.x, x[r].x, sgn * cs.y * px);
                x[r].y = fmaf(cs.x, x[r].y, sgn * cs.y * py);
            }
        } else {
            // cross-warp stage (d=10,11): partner thread t ^ (1<<(d-5)), via smem, 4 chunks
            const int pt = 1 << (d - 5);
            const float sgn = (t & pt) ? -1.f : 1.f;
            #pragma unroll 1
            for (int q = 0; q < 4; ++q) {
                __syncthreads();
                #pragma unroll
                for (int m = 0; m < 8; ++m) ex[rp][m * 128 + t] = x[q * 8 + m];
                __syncthreads();
                #pragma unroll
                for (int m = 0; m < 8; ++m) {
                    const int r = q * 8 + m;
                    float2 p = ex[rp][m * 128 + (t ^ pt)];
                    int k = (ktw | rotl12(r << 5, sm)) & 0x7FF;
                    float2 cs = stab[k];
                    x[r].x = fmaf(cs.x, x[r].x, sgn * cs.y * p.x);
                    x[r].y = fmaf(cs.x, x[r].y, sgn * cs.y * p.y);
                }
            }
        }
    }

    // ---- output: out[j] = b_32[j] (identity permutation, fully coalesced) ----
    float* o0 = O + r0base * WIDTH;
    float* o1 = O + (r0base + 1) * WIDTH;
    #pragma unroll
    for (int r = 0; r < 32; ++r) {
        int i = (w << 10) | (r << 5) | lane;
        o0[i] = x[r].x;
        o1[i] = x[r].y;
    }
}

extern "C" void kernel_launch(void* const* d_in, const int* in_sizes, int n_in,
                              void* d_out, int out_size) {
    const float* X = (const float*)d_in[0];
    const float* P = (const float*)d_in[1];
    if (n_in >= 2 && in_sizes[0] == DEPTH * HALFW) { const float* tmp = X; X = P; P = tmp; }
    float* O = (float*)d_out;
    ob_tables<<<(DEPTH * HALFW + 255) / 256, 256>>>(P);
    ob_main<<<BATCH / 4, 256>>>(X, O);
}

// round 6
// speedup vs baseline: 1.6930x; 1.6930x over previous
#include <cuda_runtime.h>
#include <cuda_bf16.h>

#define WIDTH 4096
#define HALFW 2048
#define DEPTH 32
#define BATCH 16384

// Per-stage (cos,sin) tables, PRE-PERMUTED so the main kernel's smem reads are
// conflict-free: g_tab[s][j'] where j' = 11-bit index formed by deleting pair-bit
// d=(7-s)%12 from the 12-bit position j. Built by prologue kernel. 512 KB.
__device__ float2 g_tab[DEPTH][HALFW];

__global__ void ob_tables(const float* __restrict__ P) {
    int idx = blockIdx.x * blockDim.x + threadIdx.x;
    if (idx >= DEPTH * HALFW) return;
    int s  = idx >> 11;
    int jp = idx & 2047;                      // j' (11-bit, bit d removed)
    int d  = (7 - s) % 12; if (d < 0) d += 12;
    int sm = (s + 4) % 12;
    int j0 = ((jp >> d) << (d + 1)) | (jp & ((1 << d) - 1));   // reinsert 0 at bit d
    int k  = ((j0 << sm) | (j0 >> (12 - sm))) & 0x7FF;         // angle index
    float th = P[k * DEPTH + s];              // params is (HALF, DEPTH) row-major
    g_tab[s][jp] = make_float2(cosf(th), sinf(th));
}

// Fixed layout: b_s[j] = z_s[rotl_{4+s}(j)].
// Stage s: pair rotation on bit d=(7-s)%12, sign from bit d of j.
// Input: b_0[j] = X[rotl4(j)]. Output: out[j] = b_32[j] (identity, coalesced).
__global__ __launch_bounds__(256, 2)
void ob_main(const float* __restrict__ X, float* __restrict__ O) {
    __shared__ float2 tab[2][HALFW];   // 32 KB double-buffered stage table
    __shared__ float2 ex[2][1024];     // 16 KB cross-warp exchange buffer

    const int tid  = threadIdx.x;
    const int rp   = tid >> 7;         // row-pair within CTA (0/1)
    const int t    = tid & 127;
    const int lane = t & 31;           // j bits 0..4
    const int w    = t >> 5;           // j bits 10..11
    const long r0base = (long)blockIdx.x * 4 + rp * 2;

    float2 x[32];                      // .x=row r0base, .y=row r0base+1; reg idx = j bits 5..9

    // ---- prefetch stage-0 table (linear copy, 64B per thread) ----
    #pragma unroll
    for (int c = 0; c < 4; ++c) {
        int e = (c * 256 + tid) * 2;   // float2 index, 16B chunk
        unsigned dst = (unsigned)__cvta_generic_to_shared(&tab[0][e]);
        asm volatile("cp.async.ca.shared.global [%0], [%1], 16;" :: "r"(dst), "l"(&g_tab[0][e]));
    }
    asm volatile("cp.async.commit_group;");

    // ---- input: b_0[j] = X[row][rotl4(j)] ----
    // rotl4(j) = (lane<<4)|((r&7)<<9)|(r>>3)|(w<<2); 4 consecutive floats at
    // (r>>3)=0..3 are registers m, m+8, m+16, m+24 -> one float4 each.
    {
        const float4* s0 = (const float4*)(X + r0base * WIDTH);
        const float4* s1 = (const float4*)(X + (r0base + 1) * WIDTH);
        #pragma unroll
        for (int m = 0; m < 8; ++m) {
            int i4 = (lane << 2) | (m << 7) | w;
            float4 v0 = s0[i4];
            float4 v1 = s1[i4];
            x[m].x = v0.x; x[m + 8].x = v0.y; x[m + 16].x = v0.z; x[m + 24].x = v0.w;
            x[m].y = v1.x; x[m + 8].y = v1.y; x[m + 16].y = v1.z; x[m + 24].y = v1.w;
        }
    }

    // ---- 32 stages, table double-buffered via cp.async ----
    #pragma unroll 1
    for (int s = 0; s < DEPTH; ++s) {
        __syncthreads();   // all threads done with the buffer we are about to overwrite
        if (s + 1 < DEPTH) {
            const int nb = (s + 1) & 1;
            #pragma unroll
            for (int c = 0; c < 4; ++c) {
                int e = (c * 256 + tid) * 2;
                unsigned dst = (unsigned)__cvta_generic_to_shared(&tab[nb][e]);
                asm volatile("cp.async.ca.shared.global [%0], [%1], 16;" :: "r"(dst), "l"(&g_tab[s + 1][e]));
            }
        }
        asm volatile("cp.async.commit_group;");   // always commit so wait_group 1 is exact
        asm volatile("cp.async.wait_group 1;");   // stage-s table landed (for this thread)
        __syncthreads();                          // ...and for all threads

        const float2* T = tab[s & 1];
        int d = (7 - s) % 12; if (d < 0) d += 12;

        if (d >= 5 && d <= 9) {
            // register stage: partner differs in bit (d-5) of r. addr = (w<<9)|(rc<<5)|lane.
            const int pb = 1 << (d - 5);
            const int abase = (w << 9) | lane;
            #pragma unroll
            for (int rc = 0; rc < 16; ++rc) {
                const int r0 = ((rc & ~(pb - 1)) << 1) | (rc & (pb - 1));
                const int r1 = r0 | pb;
                float2 cs = T[abase | (rc << 5)];
                float2 a = x[r0], b = x[r1];
                x[r0].x = fmaf(cs.x, a.x,  cs.y * b.x);
                x[r0].y = fmaf(cs.x, a.y,  cs.y * b.y);
                x[r1].x = fmaf(cs.x, b.x, -cs.y * a.x);
                x[r1].y = fmaf(cs.x, b.y, -cs.y * a.y);
            }
        } else if (d <= 4) {
            // lane stage: partner lane ^ (1<<d). addr = (w<<9)|(r<<4)|lane' (pair-broadcast).
            const int pb = 1 << d;
            const float sgn = (lane & pb) ? -1.f : 1.f;
            const int lanep = ((lane >> (d + 1)) << d) | (lane & (pb - 1));
            const int abase = (w << 9) | lanep;
            #pragma unroll
            for (int r = 0; r < 32; ++r) {
                float2 cs = T[abase | (r << 4)];
                float px = __shfl_xor_sync(0xffffffffu, x[r].x, pb);
                float py = __shfl_xor_sync(0xffffffffu, x[r].y, pb);
                x[r].x = fmaf(cs.x, x[r].x, sgn * cs.y * px);
                x[r].y = fmaf(cs.x, x[r].y, sgn * cs.y * py);
            }
        } else {
            // cross-warp stage (d=10,11): partner thread t ^ (1<<(d-5)), via smem, 4 chunks.
            const int pt = 1 << (d - 5);
            const float sgn = (t & pt) ? -1.f : 1.f;
            const int wp = (d == 10) ? (w >> 1) : (w & 1);
            const int abase = (wp << 10) | lane;
            #pragma unroll 1
            for (int q = 0; q < 4; ++q) {
                __syncthreads();
                #pragma unroll
                for (int m = 0; m < 8; ++m) ex[rp][m * 128 + t] = x[q * 8 + m];
                __syncthreads();
                #pragma unroll
                for (int m = 0; m < 8; ++m) {
                    const int r = q * 8 + m;
                    float2 p = ex[rp][m * 128 + (t ^ pt)];
                    float2 cs = T[abase | (r << 5)];
                    x[r].x = fmaf(cs.x, x[r].x, sgn * cs.y * p.x);
                    x[r].y = fmaf(cs.x, x[r].y, sgn * cs.y * p.y);
                }
            }
        }
    }

    // ---- output: out[j] = b_32[j] (identity permutation, fully coalesced) ----
    float* o0 = O + r0base * WIDTH;
    float* o1 = O + (r0base + 1) * WIDTH;
    #pragma unroll
    for (int r = 0; r < 32; ++r) {
        int i = (w << 10) | (r << 5) | lane;
        o0[i] = x[r].x;
        o1[i] = x[r].y;
    }
}

extern "C" void kernel_launch(void* const* d_in, const int* in_sizes, int n_in,
                              void* d_out, int out_size) {
    const float* X = (const float*)d_in[0];
    const float* P = (const float*)d_in[1];
    if (n_in >= 2 && in_sizes[0] == DEPTH * HALFW) { const float* tmp = X; X = P; P = tmp; }
    float* O = (float*)d_out;
    ob_tables<<<(DEPTH * HALFW + 255) / 256, 256>>>(P);
    ob_main<<<BATCH / 4, 256>>>(X, O);
}

// round 7
// speedup vs baseline: 1.7353x; 1.0250x over previous
#include <cuda_runtime.h>
#include <cuda_bf16.h>

#define WIDTH 4096
#define HALFW 2048
#define DEPTH 32
#define BATCH 16384

// Per-stage (cos,sin) tables, PRE-PERMUTED so the main kernel's smem reads are
// conflict-free: g_tab[s][j'] where j' = 11-bit index formed by deleting pair-bit
// d=(7-s)%12 from the 12-bit position j. Built by prologue kernel. 512 KB.
__device__ float2 g_tab[DEPTH][HALFW];

__global__ void ob_tables(const float* __restrict__ P) {
    int idx = blockIdx.x * blockDim.x + threadIdx.x;
    if (idx >= DEPTH * HALFW) return;
    int s  = idx >> 11;
    int jp = idx & 2047;                      // j' (11-bit, bit d removed)
    int d  = (7 - s) % 12; if (d < 0) d += 12;
    int sm = (s + 4) % 12;
    int j0 = ((jp >> d) << (d + 1)) | (jp & ((1 << d) - 1));   // reinsert 0 at bit d
    int k  = ((j0 << sm) | (j0 >> (12 - sm))) & 0x7FF;         // angle index
    float th = P[k * DEPTH + s];              // params is (HALF, DEPTH) row-major
    g_tab[s][jp] = make_float2(cosf(th), sinf(th));
}

// Fixed layout: b_s[j] = z_s[rotl_{4+s}(j)].
// Stage s: pair rotation on bit d=(7-s)%12, sign from bit d of j.
// Input: b_0[j] = X[rotl4(j)]. Output: out[j] = b_32[j] (identity, coalesced).
__global__ __launch_bounds__(256, 3)
void ob_main(const float* __restrict__ X, float* __restrict__ O) {
    __shared__ float2 tab[2][HALFW];   // 32 KB double-buffered stage table
    __shared__ float2 ex[2][1024];     // 16 KB cross-warp exchange buffer

    const int tid  = threadIdx.x;
    const int rp   = tid >> 7;         // row-pair within CTA (0/1)
    const int t    = tid & 127;
    const int lane = t & 31;           // j bits 0..4
    const int w    = t >> 5;           // j bits 10..11
    const long r0base = (long)blockIdx.x * 4 + rp * 2;

    float2 x[32];                      // .x=row r0base, .y=row r0base+1; reg idx = j bits 5..9

    // ---- prefetch stage-0 table (linear copy, 64B per thread) ----
    #pragma unroll
    for (int c = 0; c < 4; ++c) {
        int e = (c * 256 + tid) * 2;   // float2 index, 16B chunk
        unsigned dst = (unsigned)__cvta_generic_to_shared(&tab[0][e]);
        asm volatile("cp.async.ca.shared.global [%0], [%1], 16;" :: "r"(dst), "l"(&g_tab[0][e]));
    }
    asm volatile("cp.async.commit_group;");

    // ---- input: b_0[j] = X[row][rotl4(j)] ----
    // rotl4(j) = (lane<<4)|((r&7)<<9)|(r>>3)|(w<<2); 4 consecutive floats at
    // (r>>3)=0..3 are registers m, m+8, m+16, m+24 -> one float4 each.
    {
        const float4* s0 = (const float4*)(X + r0base * WIDTH);
        const float4* s1 = (const float4*)(X + (r0base + 1) * WIDTH);
        #pragma unroll
        for (int m = 0; m < 8; ++m) {
            int i4 = (lane << 2) | (m << 7) | w;
            float4 v0 = s0[i4];
            float4 v1 = s1[i4];
            x[m].x = v0.x; x[m + 8].x = v0.y; x[m + 16].x = v0.z; x[m + 24].x = v0.w;
            x[m].y = v1.x; x[m + 8].y = v1.y; x[m + 16].y = v1.z; x[m + 24].y = v1.w;
        }
    }

    // ---- 32 stages, table double-buffered via cp.async ----
    #pragma unroll 1
    for (int s = 0; s < DEPTH; ++s) {
        __syncthreads();   // all threads done with the buffer we are about to overwrite
        if (s + 1 < DEPTH) {
            const int nb = (s + 1) & 1;
            #pragma unroll
            for (int c = 0; c < 4; ++c) {
                int e = (c * 256 + tid) * 2;
                unsigned dst = (unsigned)__cvta_generic_to_shared(&tab[nb][e]);
                asm volatile("cp.async.ca.shared.global [%0], [%1], 16;" :: "r"(dst), "l"(&g_tab[s + 1][e]));
            }
        }
        asm volatile("cp.async.commit_group;");   // always commit so wait_group 1 is exact
        asm volatile("cp.async.wait_group 1;");   // stage-s table landed (for this thread)
        __syncthreads();                          // ...and for all threads

        const float2* __restrict__ T = tab[s & 1];
        int d = (7 - s) % 12; if (d < 0) d += 12;

        if (d >= 5 && d <= 9) {
            // register stage: partner differs in bit (d-5) of r. addr = (w<<9)|(rc<<5)|lane.
            const int pb = 1 << (d - 5);
            const int abase = (w << 9) | lane;
            #pragma unroll
            for (int rc = 0; rc < 16; ++rc) {
                const int r0 = ((rc & ~(pb - 1)) << 1) | (rc & (pb - 1));
                const int r1 = r0 | pb;
                float2 cs = T[abase | (rc << 5)];
                float2 a = x[r0], b = x[r1];
                x[r0].x = fmaf(cs.x, a.x,  cs.y * b.x);
                x[r0].y = fmaf(cs.x, a.y,  cs.y * b.y);
                x[r1].x = fmaf(cs.x, b.x, -cs.y * a.x);
                x[r1].y = fmaf(cs.x, b.y, -cs.y * a.y);
            }
        } else if (d <= 4) {
            // lane stage: partner lane ^ (1<<d). addr = (w<<9)|(r<<4)|lane' (pair-broadcast).
            const int pb = 1 << d;
            const float sgn = (lane & pb) ? -1.f : 1.f;
            const int lanep = ((lane >> (d + 1)) << d) | (lane & (pb - 1));
            const int abase = (w << 9) | lanep;
            #pragma unroll
            for (int r = 0; r < 32; ++r) {
                float2 cs = T[abase | (r << 4)];
                float px = __shfl_xor_sync(0xffffffffu, x[r].x, pb);
                float py = __shfl_xor_sync(0xffffffffu, x[r].y, pb);
                x[r].x = fmaf(cs.x, x[r].x, sgn * cs.y * px);
                x[r].y = fmaf(cs.x, x[r].y, sgn * cs.y * py);
            }
        } else {
            // cross-warp stage (d=10,11): partner thread t ^ (1<<(d-5)), via smem, 4 chunks.
            const int pt = 1 << (d - 5);
            const float sgn = (t & pt) ? -1.f : 1.f;
            const int wp = (d == 10) ? (w >> 1) : (w & 1);
            const int abase = (wp << 10) | lane;
            #pragma unroll 1
            for (int q = 0; q < 4; ++q) {
                __syncthreads();
                #pragma unroll
                for (int m = 0; m < 8; ++m) ex[rp][m * 128 + t] = x[q * 8 + m];
                __syncthreads();
                #pragma unroll
                for (int m = 0; m < 8; ++m) {
                    const int r = q * 8 + m;
                    float2 p = ex[rp][m * 128 + (t ^ pt)];
                    float2 cs = T[abase | (r << 5)];
                    x[r].x = fmaf(cs.x, x[r].x, sgn * cs.y * p.x);
                    x[r].y = fmaf(cs.x, x[r].y, sgn * cs.y * p.y);
                }
            }
        }
    }

    // ---- output: out[j] = b_32[j] (identity permutation, fully coalesced) ----
    float* o0 = O + r0base * WIDTH;
    float* o1 = O + (r0base + 1) * WIDTH;
    #pragma unroll
    for (int r = 0; r < 32; ++r) {
        int i = (w << 10) | (r << 5) | lane;
        o0[i] = x[r].x;
        o1[i] = x[r].y;
    }
}

extern "C" void kernel_launch(void* const* d_in, const int* in_sizes, int n_in,
                              void* d_out, int out_size) {
    const float* X = (const float*)d_in[0];
    const float* P = (const float*)d_in[1];
    if (n_in >= 2 && in_sizes[0] == DEPTH * HALFW) { const float* tmp = X; X = P; P = tmp; }
    float* O = (float*)d_out;
    ob_tables<<<(DEPTH * HALFW + 255) / 256, 256>>>(P);
    ob_main<<<BATCH / 4, 256>>>(X, O);
}

// round 9
// speedup vs baseline: 3.1832x; 1.8344x over previous
#include <cuda_runtime.h>
#include <cuda_bf16.h>

#define WIDTH 4096
#define HALFW 2048
#define DEPTH 32
#define BATCH 16384

// ---- group bit-mappings (single source of truth for prologue + main) ----
// Group g holds j-bits RMAP[g] in the 5 register bits, LMAP[g] in the 5 lane
// bits, WMAP[g] in the 2 warp bits. Group 7 is the LOAD mapping.
__device__ constexpr int LMAP[8][5] = {
    {0,1,2,8,9},   // G0  (stages 0-4,   d=7,6,5,4,3)
    {5,6,7,8,9},   // G1  (stages 5-9,   d=2,1,0,11,10)
    {0,1,2,3,4},   // G2  (stages 10-14, d=9,8,7,6,5)
    {5,6,7,8,9},   // G3  (stages 15-19, d=4,3,2,1,0)
    {0,1,2,3,4},   // G4  (stages 20-24, d=11,10,9,8,7)
    {0,1,7,8,9},   // G5  (stages 25-29, d=6,5,4,3,2)
    {2,3,4,5,6},   // G6  (stages 30-31, d=1,0) -> coalesced store
    {10,11,0,1,2}  // G7 = LOAD
};
__device__ constexpr int RMAP[8][5] = {
    {3,4,5,6,7},
    {0,1,2,10,11},
    {5,6,7,8,9},
    {0,1,2,3,4},
    {7,8,9,10,11},
    {2,3,4,5,6},
    {0,1,7,8,9},
    {5,6,7,8,9}
};
__device__ constexpr int WMAP[8][2] = {
    {10,11},{3,4},{10,11},{10,11},{5,6},{10,11},{10,11},{3,4}
};
// pair-bit position p in RMAP[g] per stage, and group per stage
__device__ constexpr int CP[DEPTH] = {4,3,2,1,0, 2,1,0,4,3, 4,3,2,1,0, 4,3,2,1,0,
                                      4,3,2,1,0, 4,3,2,1,0, 1,0};
__device__ constexpr int CG[DEPTH] = {0,0,0,0,0,1,1,1,1,1,2,2,2,2,2,3,3,3,3,3,
                                      4,4,4,4,4,5,5,5,5,5,6,6};

// GF(2)-linear smem swizzle (slot sets {0,5},{1,6},{2,7},{3,8,10},{4,9,11})
__device__ constexpr int csig(int j) {
    return j ^ ((j >> 5) & 31) ^ (((j >> 10) & 3) << 3);
}
__device__ constexpr int scat5(int v, const int* m) {
    return ((v & 1) << m[0]) | (((v >> 1) & 1) << m[1]) | (((v >> 2) & 1) << m[2])
         | (((v >> 3) & 1) << m[3]) | (((v >> 4) & 1) << m[4]);
}

// Per-stage (cos,sin) tables pre-permuted into slot order (w<<9)|(rc<<5)|lane
// under the stage's group mapping. 512 KB __device__ global.
__device__ float2 g_tab[DEPTH][HALFW];

__global__ void ob_tables(const float* __restrict__ P) {
    int idx = blockIdx.x * blockDim.x + threadIdx.x;
    if (idx >= DEPTH * HALFW) return;
    int s = idx >> 11, u = idx & 2047;
    int g = CG[s], p = CP[s], sm = (s + 4) % 12;
    int lane = u & 31, rc = (u >> 5) & 15, w = u >> 9;
    int r0 = ((rc >> p) << (p + 1)) | (rc & ((1 << p) - 1));   // insert 0 at bit p
    int j = 0;
    for (int t = 0; t < 5; ++t) j |= ((lane >> t) & 1) << LMAP[g][t];
    for (int t = 0; t < 5; ++t) j |= ((r0 >> t) & 1) << RMAP[g][t];
    for (int t = 0; t < 2; ++t) j |= ((w >> t) & 1) << WMAP[g][t];
    int k = (((j << sm) | (j >> (12 - sm))) & 0xFFF) & 0x7FF;  // angle index
    float th = P[k * DEPTH + s];                               // params (HALF, DEPTH)
    g_tab[s][u] = make_float2(cosf(th), sinf(th));
}

// transpose register data from group GF mapping to group GT mapping via S
template<int GF, int GT>
__device__ __forceinline__ void xpose(float2* x, float* S, int lane, int w, int rpoff) {
    int lwo = 0, lwn = 0;
    #pragma unroll
    for (int t = 0; t < 5; ++t) {
        lwo |= ((lane >> t) & 1) << LMAP[GF][t];
        lwn |= ((lane >> t) & 1) << LMAP[GT][t];
    }
    #pragma unroll
    for (int t = 0; t < 2; ++t) {
        lwo |= ((w >> t) & 1) << WMAP[GF][t];
        lwn |= ((w >> t) & 1) << WMAP[GT][t];
    }
    const int so = csig(lwo), sn = csig(lwn);
    __syncthreads();
    #pragma unroll
    for (int r = 0; r < 32; ++r) S[rpoff + (so ^ csig(scat5(r, RMAP[GF])))] = x[r].x;
    __syncthreads();
    #pragma unroll
    for (int r = 0; r < 32; ++r) x[r].x = S[rpoff + (sn ^ csig(scat5(r, RMAP[GT])))];
    __syncthreads();
    #pragma unroll
    for (int r = 0; r < 32; ++r) S[rpoff + (so ^ csig(scat5(r, RMAP[GF])))] = x[r].y;
    __syncthreads();
    #pragma unroll
    for (int r = 0; r < 32; ++r) x[r].y = S[rpoff + (sn ^ csig(scat5(r, RMAP[GT])))];
}

template<int P>
__device__ __forceinline__ void stage_body(float2* x, const float2* __restrict__ T, int abase) {
    #pragma unroll
    for (int rc = 0; rc < 16; ++rc) {
        const int r0 = ((rc >> P) << (P + 1)) | (rc & ((1 << P) - 1));
        const int r1 = r0 | (1 << P);
        float2 cs = T[abase | (rc << 5)];
        float2 a = x[r0], b = x[r1];
        x[r0].x = fmaf(cs.x, a.x,  cs.y * b.x);
        x[r0].y = fmaf(cs.x, a.y,  cs.y * b.y);
        x[r1].x = fmaf(cs.x, b.x, -cs.y * a.x);
        x[r1].y = fmaf(cs.x, b.y, -cs.y * a.y);
    }
}

__global__ __launch_bounds__(256, 3)
void ob_main(const float* __restrict__ X, float* __restrict__ O) {
    extern __shared__ char smem[];
    float2 (*tab)[HALFW] = (float2(*)[HALFW])smem;          // 32 KB double buffer
    float* S = (float*)(smem + 2 * HALFW * sizeof(float2)); // 32 KB transpose buf

    const int tid  = threadIdx.x;
    const int rp   = tid >> 7;          // row-pair in CTA (0/1)
    const int t    = tid & 127;
    const int lane = t & 31;
    const int w    = t >> 5;
    const int rpoff = rp << 12;         // 4096 floats per row-pair in S
    const long r0base = (long)blockIdx.x * 4 + rp * 2;
    const int abase = (w << 9) | lane;

    float2 x[32];

    // ---- prefetch stage-0 table ----
    #pragma unroll
    for (int c = 0; c < 4; ++c) {
        int e = (c * 256 + tid) * 2;
        unsigned dst = (unsigned)__cvta_generic_to_shared(&tab[0][e]);
        asm volatile("cp.async.ca.shared.global [%0], [%1], 16;" :: "r"(dst), "l"(&g_tab[0][e]));
    }
    asm volatile("cp.async.commit_group;");

    // ---- coalesced load under LOAD mapping (G7): r = (c<<3)|m ----
    {
        const float4* s0 = (const float4*)(X + r0base * WIDTH);
        const float4* s1 = (const float4*)(X + (r0base + 1) * WIDTH);
        #pragma unroll
        for (int m = 0; m < 8; ++m) {
            int a4 = (m << 7) | (w << 5) | lane;
            float4 v0 = s0[a4], v1 = s1[a4];
            x[m].x = v0.x; x[8 + m].x = v0.y; x[16 + m].x = v0.z; x[24 + m].x = v0.w;
            x[m].y = v1.x; x[8 + m].y = v1.y; x[16 + m].y = v1.z; x[24 + m].y = v1.w;
        }
    }

    xpose<7, 0>(x, S, lane, w, rpoff);   // LOAD -> G0

    // ---- 32 stages, all register stages; transpose at group boundaries ----
    #pragma unroll 1
    for (int s = 0; s < DEPTH; ++s) {
        switch (s) {
            case 5:  xpose<0, 1>(x, S, lane, w, rpoff); break;
            case 10: xpose<1, 2>(x, S, lane, w, rpoff); break;
            case 15: xpose<2, 3>(x, S, lane, w, rpoff); break;
            case 20: xpose<3, 4>(x, S, lane, w, rpoff); break;
            case 25: xpose<4, 5>(x, S, lane, w, rpoff); break;
            case 30: xpose<5, 6>(x, S, lane, w, rpoff); break;
            default: break;
        }
        __syncthreads();   // everyone done with the tab buffer being overwritten
        if (s + 1 < DEPTH) {
            const int nb = (s + 1) & 1;
            #pragma unroll
            for (int c = 0; c < 4; ++c) {
                int e = (c * 256 + tid) * 2;
                unsigned dst = (unsigned)__cvta_generic_to_shared(&tab[nb][e]);
                asm volatile("cp.async.ca.shared.global [%0], [%1], 16;" :: "r"(dst), "l"(&g_tab[s + 1][e]));
            }
        }
        asm volatile("cp.async.commit_group;");
        asm volatile("cp.async.wait_group 1;");
        __syncthreads();

        const float2* __restrict__ T = tab[s & 1];
        switch (CP[s]) {
            case 0: stage_body<0>(x, T, abase); break;
            case 1: stage_body<1>(x, T, abase); break;
            case 2: stage_body<2>(x, T, abase); break;
            case 3: stage_body<3>(x, T, abase); break;
            default: stage_body<4>(x, T, abase); break;
        }
    }

    // ---- store under G6 mapping: out[j]=b32[j], float4-coalesced ----
    {
        float4* o0 = (float4*)(O + r0base * WIDTH);
        float4* o1 = (float4*)(O + (r0base + 1) * WIDTH);
        #pragma unroll
        for (int e = 0; e < 8; ++e) {
            int j4 = (w << 8) | (e << 5) | lane;
            o0[j4] = make_float4(x[e*4].x, x[e*4+1].x, x[e*4+2].x, x[e*4+3].x);
            o1[j4] = make_float4(x[e*4].y, x[e*4+1].y, x[e*4+2].y, x[e*4+3].y);
        }
    }
}

extern "C" void kernel_launch(void* const* d_in, const int* in_sizes, int n_in,
                              void* d_out, int out_size) {
    const float* X = (const float*)d_in[0];
    const float* P = (const float*)d_in[1];
    if (n_in >= 2 && in_sizes[0] == DEPTH * HALFW) { const float* tmp = X; X = P; P = tmp; }
    float* O = (float*)d_out;
    const int smem = 2 * HALFW * sizeof(float2) + WIDTH * 2 * sizeof(float);  // 64 KB
    cudaFuncSetAttribute(ob_main, cudaFuncAttributeMaxDynamicSharedMemorySize, smem);
    ob_tables<<<(DEPTH * HALFW + 255) / 256, 256>>>(P);
    ob_main<<<BATCH / 4, 256, smem>>>(X, O);
}

// round 10
// speedup vs baseline: 5.4347x; 1.7073x over previous
#include <cuda_runtime.h>
#include <cuda_bf16.h>

#define WIDTH 4096
#define HALFW 2048
#define DEPTH 32
#define BATCH 16384

// ---- group bit-mappings (single source of truth for prologue + main) ----
__device__ constexpr int LMAP[8][5] = {
    {0,1,2,8,9},   // G0  (stages 0-4,   d=7,6,5,4,3)
    {5,6,7,8,9},   // G1  (stages 5-9,   d=2,1,0,11,10)
    {0,1,2,3,4},   // G2  (stages 10-14, d=9,8,7,6,5)
    {5,6,7,8,9},   // G3  (stages 15-19, d=4,3,2,1,0)
    {0,1,2,3,4},   // G4  (stages 20-24, d=11,10,9,8,7)
    {0,1,7,8,9},   // G5  (stages 25-29, d=6,5,4,3,2)
    {2,3,4,5,6},   // G6  (stages 30-31, d=1,0) -> coalesced store
    {10,11,0,1,2}  // G7 = LOAD
};
__device__ constexpr int RMAP[8][5] = {
    {3,4,5,6,7},
    {0,1,2,10,11},
    {5,6,7,8,9},
    {0,1,2,3,4},
    {7,8,9,10,11},
    {2,3,4,5,6},
    {0,1,7,8,9},
    {5,6,7,8,9}
};
__device__ constexpr int WMAP[8][2] = {
    {10,11},{3,4},{10,11},{10,11},{5,6},{10,11},{10,11},{3,4}
};
__device__ constexpr int CP[DEPTH] = {4,3,2,1,0, 2,1,0,4,3, 4,3,2,1,0, 4,3,2,1,0,
                                      4,3,2,1,0, 4,3,2,1,0, 1,0};
__device__ constexpr int CG[DEPTH] = {0,0,0,0,0,1,1,1,1,1,2,2,2,2,2,3,3,3,3,3,
                                      4,4,4,4,4,5,5,5,5,5,6,6};

// GF(2)-linear smem swizzle (slot sets {0,5},{1,6},{2,7},{3,8,10},{4,9,11})
__device__ constexpr int csig(int j) {
    return j ^ ((j >> 5) & 31) ^ (((j >> 10) & 3) << 3);
}
__device__ constexpr int scat5(int v, const int* m) {
    return ((v & 1) << m[0]) | (((v >> 1) & 1) << m[1]) | (((v >> 2) & 1) << m[2])
         | (((v >> 3) & 1) << m[3]) | (((v >> 4) & 1) << m[4]);
}

// Per-stage (cos,sin) tables pre-permuted into slot order (w<<9)|(rc<<5)|lane
// under the stage's group mapping. 512 KB __device__ global.
__device__ float2 g_tab[DEPTH][HALFW];

__global__ void ob_tables(const float* __restrict__ P) {
    int idx = blockIdx.x * blockDim.x + threadIdx.x;
    if (idx >= DEPTH * HALFW) return;
    int s = idx >> 11, u = idx & 2047;
    int g = CG[s], p = CP[s], sm = (s + 4) % 12;
    int lane = u & 31, rc = (u >> 5) & 15, w = u >> 9;
    int r0 = ((rc >> p) << (p + 1)) | (rc & ((1 << p) - 1));   // insert 0 at bit p
    int j = 0;
    for (int t = 0; t < 5; ++t) j |= ((lane >> t) & 1) << LMAP[g][t];
    for (int t = 0; t < 5; ++t) j |= ((r0 >> t) & 1) << RMAP[g][t];
    for (int t = 0; t < 2; ++t) j |= ((w >> t) & 1) << WMAP[g][t];
    int k = (((j << sm) | (j >> (12 - sm))) & 0xFFF) & 0x7FF;  // angle index
    float th = P[k * DEPTH + s];                               // params (HALF, DEPTH)
    g_tab[s][u] = make_float2(cosf(th), sinf(th));
}

// transpose 4-row register state from group GF mapping to GT mapping via S
// (two components per pass, paired as float2 -> STS.64/LDS.64)
template<int GF, int GT>
__device__ __forceinline__ void xpose(float4* x, float2* S, int lane, int w) {
    int lwo = 0, lwn = 0;
    #pragma unroll
    for (int t = 0; t < 5; ++t) {
        lwo |= ((lane >> t) & 1) << LMAP[GF][t];
        lwn |= ((lane >> t) & 1) << LMAP[GT][t];
    }
    #pragma unroll
    for (int t = 0; t < 2; ++t) {
        lwo |= ((w >> t) & 1) << WMAP[GF][t];
        lwn |= ((w >> t) & 1) << WMAP[GT][t];
    }
    const int so = csig(lwo), sn = csig(lwn);
    __syncthreads();
    #pragma unroll
    for (int r = 0; r < 32; ++r)
        S[so ^ csig(scat5(r, RMAP[GF]))] = make_float2(x[r].x, x[r].y);
    __syncthreads();
    #pragma unroll
    for (int r = 0; r < 32; ++r) {
        float2 v = S[sn ^ csig(scat5(r, RMAP[GT]))];
        x[r].x = v.x; x[r].y = v.y;
    }
    __syncthreads();
    #pragma unroll
    for (int r = 0; r < 32; ++r)
        S[so ^ csig(scat5(r, RMAP[GF]))] = make_float2(x[r].z, x[r].w);
    __syncthreads();
    #pragma unroll
    for (int r = 0; r < 32; ++r) {
        float2 v = S[sn ^ csig(scat5(r, RMAP[GT]))];
        x[r].z = v.x; x[r].w = v.y;
    }
}

template<int P>
__device__ __forceinline__ void stage_body(float4* x, const float2* __restrict__ T, int abase) {
    #pragma unroll
    for (int rc = 0; rc < 16; ++rc) {
        const int r0 = ((rc >> P) << (P + 1)) | (rc & ((1 << P) - 1));
        const int r1 = r0 | (1 << P);
        float2 cs = T[abase | (rc << 5)];
        const float c = cs.x, sv = cs.y, ns = -cs.y;
        float4 a = x[r0], b = x[r1];
        x[r0].x = fmaf(c, a.x, sv * b.x);  x[r1].x = fmaf(c, b.x, ns * a.x);
        x[r0].y = fmaf(c, a.y, sv * b.y);  x[r1].y = fmaf(c, b.y, ns * a.y);
        x[r0].z = fmaf(c, a.z, sv * b.z);  x[r1].z = fmaf(c, b.z, ns * a.z);
        x[r0].w = fmaf(c, a.w, sv * b.w);  x[r1].w = fmaf(c, b.w, ns * a.w);
    }
}

__global__ __launch_bounds__(128, 3)
void ob_main(const float* __restrict__ X, float* __restrict__ O) {
    extern __shared__ char smem[];
    float2 (*tab)[HALFW] = (float2(*)[HALFW])smem;          // 32 KB double buffer
    float2* S = (float2*)(smem + 2 * HALFW * sizeof(float2)); // 32 KB transpose buf

    const int tid  = threadIdx.x;        // 128 threads = one row group
    const int lane = tid & 31;
    const int w    = tid >> 5;
    const long r0base = (long)blockIdx.x * 4;
    const int abase = (w << 9) | lane;

    float4 x[32];    // components x,y,z,w = rows r0base..r0base+3

    // ---- prefetch stage-0 table (16 KB / 128 threads = 8 x 16B each) ----
    #pragma unroll
    for (int c = 0; c < 8; ++c) {
        int e = (c * 128 + tid) * 2;
        unsigned dst = (unsigned)__cvta_generic_to_shared(&tab[0][e]);
        asm volatile("cp.async.ca.shared.global [%0], [%1], 16;" :: "r"(dst), "l"(&g_tab[0][e]));
    }
    asm volatile("cp.async.commit_group;");

    // ---- coalesced load under LOAD mapping (G7): r = (c<<3)|m ----
    {
        const float4* s0 = (const float4*)(X + r0base * WIDTH);
        const float4* s1 = (const float4*)(X + (r0base + 1) * WIDTH);
        const float4* s2 = (const float4*)(X + (r0base + 2) * WIDTH);
        const float4* s3 = (const float4*)(X + (r0base + 3) * WIDTH);
        #pragma unroll
        for (int m = 0; m < 8; ++m) {
            int a4 = (m << 7) | (w << 5) | lane;
            float4 v0 = s0[a4], v1 = s1[a4], v2 = s2[a4], v3 = s3[a4];
            x[m].x      = v0.x; x[8 + m].x  = v0.y; x[16 + m].x = v0.z; x[24 + m].x = v0.w;
            x[m].y      = v1.x; x[8 + m].y  = v1.y; x[16 + m].y = v1.z; x[24 + m].y = v1.w;
            x[m].z      = v2.x; x[8 + m].z  = v2.y; x[16 + m].z = v2.z; x[24 + m].z = v2.w;
            x[m].w      = v3.x; x[8 + m].w  = v3.y; x[16 + m].w = v3.z; x[24 + m].w = v3.w;
        }
    }

    xpose<7, 0>(x, S, lane, w);   // LOAD -> G0

    // ---- 32 stages, all register stages; transpose at group boundaries ----
    #pragma unroll 1
    for (int s = 0; s < DEPTH; ++s) {
        switch (s) {
            case 5:  xpose<0, 1>(x, S, lane, w); break;
            case 10: xpose<1, 2>(x, S, lane, w); break;
            case 15: xpose<2, 3>(x, S, lane, w); break;
            case 20: xpose<3, 4>(x, S, lane, w); break;
            case 25: xpose<4, 5>(x, S, lane, w); break;
            case 30: xpose<5, 6>(x, S, lane, w); break;
            default: break;
        }
        __syncthreads();   // everyone done with the tab buffer being overwritten
        if (s + 1 < DEPTH) {
            const int nb = (s + 1) & 1;
            #pragma unroll
            for (int c = 0; c < 8; ++c) {
                int e = (c * 128 + tid) * 2;
                unsigned dst = (unsigned)__cvta_generic_to_shared(&tab[nb][e]);
                asm volatile("cp.async.ca.shared.global [%0], [%1], 16;" :: "r"(dst), "l"(&g_tab[s + 1][e]));
            }
        }
        asm volatile("cp.async.commit_group;");
        asm volatile("cp.async.wait_group 1;");
        __syncthreads();

        const float2* __restrict__ T = tab[s & 1];
        switch (CP[s]) {
            case 0: stage_body<0>(x, T, abase); break;
            case 1: stage_body<1>(x, T, abase); break;
            case 2: stage_body<2>(x, T, abase); break;
            case 3: stage_body<3>(x, T, abase); break;
            default: stage_body<4>(x, T, abase); break;
        }
    }

    // ---- store under G6 mapping: out[j]=b32[j], float4-coalesced ----
    {
        float4* o0 = (float4*)(O + r0base * WIDTH);
        float4* o1 = (float4*)(O + (r0base + 1) * WIDTH);
        float4* o2 = (float4*)(O + (r0base + 2) * WIDTH);
        float4* o3 = (float4*)(O + (r0base + 3) * WIDTH);
        #pragma unroll
        for (int e = 0; e < 8; ++e) {
            int j4 = (w << 8) | (e << 5) | lane;
            o0[j4] = make_float4(x[e*4].x, x[e*4+1].x, x[e*4+2].x, x[e*4+3].x);
            o1[j4] = make_float4(x[e*4].y, x[e*4+1].y, x[e*4+2].y, x[e*4+3].y);
            o2[j4] = make_float4(x[e*4].z, x[e*4+1].z, x[e*4+2].z, x[e*4+3].z);
            o3[j4] = make_float4(x[e*4].w, x[e*4+1].w, x[e*4+2].w, x[e*4+3].w);
        }
    }
}

extern "C" void kernel_launch(void* const* d_in, const int* in_sizes, int n_in,
                              void* d_out, int out_size) {
    const float* X = (const float*)d_in[0];
    const float* P = (const float*)d_in[1];
    if (n_in >= 2 && in_sizes[0] == DEPTH * HALFW) { const float* tmp = X; X = P; P = tmp; }
    float* O = (float*)d_out;
    const int smem = 2 * HALFW * sizeof(float2) + WIDTH * sizeof(float2);  // 64 KB
    cudaFuncSetAttribute(ob_main, cudaFuncAttributeMaxDynamicSharedMemorySize, smem);
    ob_tables<<<(DEPTH * HALFW + 255) / 256, 256>>>(P);
    ob_main<<<BATCH / 4, 128, smem>>>(X, O);
}